// round 2
// baseline (speedup 1.0000x reference)
#include <cuda_runtime.h>
#include <cstdint>
#include <cstddef>

// ---------------------------------------------------------------------------
// 2-layer GRU decoder, B=128, T=1024, H=200.
// 16 clusters x 8 CTAs. Each cluster owns 8 batch elements; each CTA owns a
// 25-wide hidden slice (75 gate rows of W_hh0 / W_ih1 / W_hh1, fp32, smem-
// resident). Hidden state broadcast per step via st.shared::cluster + 2
// barrier.cluster per step. Inner product uses packed fma.rn.f32x2.
// ---------------------------------------------------------------------------

#define HDIM   200
#define TSTEPS 1024
#define NB     8            // batch per cluster
#define HS     25           // hidden slice per CTA
#define PITCH  204          // h row pitch (floats) -> conflict-free LDS.128
#define NTHR   256
#define CLSZ   8
#define HB     (NB*PITCH)   // floats per h buffer (1632)

// ---- shared memory layout (float offsets) ----
enum {
  O_W0R  = 0,
  O_W0Z  = O_W0R  + HS*HDIM,
  O_W0N  = O_W0Z  + HS*HDIM,
  O_W1XR = O_W0N  + HS*HDIM,
  O_W1XZ = O_W1XR + HS*HDIM,
  O_W1XN = O_W1XZ + HS*HDIM,
  O_W1HR = O_W1XN + HS*HDIM,
  O_W1HZ = O_W1HR + HS*HDIM,
  O_W1HN = O_W1HZ + HS*HDIM,
  O_WI0R = O_W1HN + HS*HDIM,     // [25][8]
  O_WI0Z = O_WI0R + HS*8,
  O_WI0N = O_WI0Z + HS*8,
  O_WFC  = O_WI0N + HS*8,        // [4][200]
  O_BFC  = O_WFC  + 4*HDIM,
  O_BR0  = O_BFC  + 4,
  O_BZ0  = O_BR0  + HS,
  O_BN0H = O_BZ0  + HS,
  O_BN0X = O_BN0H + HS,
  O_BR1  = O_BN0X + HS,
  O_BZ1  = O_BR1  + HS,
  O_BN1H = O_BZ1  + HS,
  O_BN1X = O_BN1H + HS,          // ends 46604
  O_H0   = 46608,                // [2][HB], 16B aligned
  O_H1   = O_H0 + 2*HB,
  O_INB  = O_H1 + 2*HB,          // [8][8]
  SMEM_F = O_INB + NB*8
};
#define SMEM_BYTES (SMEM_F*4)

// ---- PTX helpers ----
#define LDSV2(a_, b_, addr_) \
  asm volatile("ld.shared.v2.u64 {%0,%1},[%2];" : "=l"(a_), "=l"(b_) : "r"(addr_))

#define FMA2(acc_, a_, b_) \
  asm("fma.rn.f32x2 %0, %1, %2, %0;" : "+l"(acc_) : "l"(a_), "l"(b_))

__device__ __forceinline__ float red2(unsigned long long v) {
  float lo, hi;
  asm("mov.b64 {%0,%1}, %2;" : "=f"(lo), "=f"(hi) : "l"(v));
  return lo + hi;
}

__device__ __forceinline__ void cluster_sync() {
  asm volatile("barrier.cluster.arrive.aligned;" ::: "memory");
  asm volatile("barrier.cluster.wait.aligned;" ::: "memory");
}

__device__ __forceinline__ float sigmoid_f(float x) {
  return __fdividef(1.0f, 1.0f + __expf(-x));
}
__device__ __forceinline__ float tanh_f(float x) {
  float e = __expf(-2.0f * x);
  return __fdividef(2.0f, 1.0f + e) - 1.0f;
}

extern __shared__ float smem[];

__global__ void __launch_bounds__(NTHR, 1) __cluster_dims__(CLSZ, 1, 1)
gru2_kernel(const float* __restrict__ x,
            const float* __restrict__ W_ih0, const float* __restrict__ W_hh0,
            const float* __restrict__ b_ih0, const float* __restrict__ b_hh0,
            const float* __restrict__ W_ih1, const float* __restrict__ W_hh1,
            const float* __restrict__ b_ih1, const float* __restrict__ b_hh1,
            const float* __restrict__ W_fc,  const float* __restrict__ b_fc,
            float* __restrict__ out)
{
  const int tid = threadIdx.x;
  uint32_t rank;
  asm("mov.u32 %0, %%cluster_ctarank;" : "=r"(rank));
  const int g    = blockIdx.x >> 3;       // cluster (batch group) id
  const int row0 = (int)rank * HS;        // global hidden slice start

  // ---- load weights into smem (each slice is a contiguous gmem chunk) ----
  {
    auto cp4 = [&](int dstF, const float* src, int nF) {
      float4* d = (float4*)(smem + dstF);
      const float4* s = (const float4*)src;
      const int n4 = nF >> 2;
      for (int i = tid; i < n4; i += NTHR) d[i] = s[i];
    };
    cp4(O_W0R,  W_hh0 + (size_t)(         row0) * HDIM, HS*HDIM);
    cp4(O_W0Z,  W_hh0 + (size_t)(  HDIM + row0) * HDIM, HS*HDIM);
    cp4(O_W0N,  W_hh0 + (size_t)(2*HDIM + row0) * HDIM, HS*HDIM);
    cp4(O_W1XR, W_ih1 + (size_t)(         row0) * HDIM, HS*HDIM);
    cp4(O_W1XZ, W_ih1 + (size_t)(  HDIM + row0) * HDIM, HS*HDIM);
    cp4(O_W1XN, W_ih1 + (size_t)(2*HDIM + row0) * HDIM, HS*HDIM);
    cp4(O_W1HR, W_hh1 + (size_t)(         row0) * HDIM, HS*HDIM);
    cp4(O_W1HZ, W_hh1 + (size_t)(  HDIM + row0) * HDIM, HS*HDIM);
    cp4(O_W1HN, W_hh1 + (size_t)(2*HDIM + row0) * HDIM, HS*HDIM);
    cp4(O_WI0R, W_ih0 + (size_t)(         row0) * 8, HS*8);
    cp4(O_WI0Z, W_ih0 + (size_t)(  HDIM + row0) * 8, HS*8);
    cp4(O_WI0N, W_ih0 + (size_t)(2*HDIM + row0) * 8, HS*8);
    cp4(O_WFC,  W_fc, 4*HDIM);
    if (tid < 4) smem[O_BFC + tid] = b_fc[tid];
    if (tid < HS) {
      int J = row0 + tid;
      smem[O_BR0  + tid] = b_ih0[J]          + b_hh0[J];
      smem[O_BZ0  + tid] = b_ih0[HDIM + J]   + b_hh0[HDIM + J];
      smem[O_BN0X + tid] = b_ih0[2*HDIM + J];
      smem[O_BN0H + tid] = b_hh0[2*HDIM + J];
      smem[O_BR1  + tid] = b_ih1[J]          + b_hh1[J];
      smem[O_BZ1  + tid] = b_ih1[HDIM + J]   + b_hh1[HDIM + J];
      smem[O_BN1X + tid] = b_ih1[2*HDIM + J];
      smem[O_BN1H + tid] = b_hh1[2*HDIM + J];
    }
    // zero hidden state buffers (both parities)
    for (int i = tid; i < 2*HB; i += NTHR) { smem[O_H0 + i] = 0.f; smem[O_H1 + i] = 0.f; }
    // init step-0 inputs: tf = ones, emotion = x[b, 0, 4:8]
    if (tid < NB) {
      const float* xr = x + (size_t)(g*NB + tid) * TSTEPS * 8;
      float* ib = smem + O_INB + tid*8;
      ib[0] = 1.f; ib[1] = 1.f; ib[2] = 1.f; ib[3] = 1.f;
      ib[4] = xr[4]; ib[5] = xr[5]; ib[6] = xr[6]; ib[7] = xr[7];
    }
  }
  cluster_sync();   // all init done cluster-wide before any remote h writes

  // ---- per-thread constants ----
  const int j = tid >> 3;          // local hidden idx (valid for tid<200)
  const int b = tid & 7;           // local batch idx
  uint32_t sb = (uint32_t)__cvta_generic_to_shared(smem);
  const uint32_t aw0r  = sb + (O_W0R  + j*HDIM)*4;
  const uint32_t aw0z  = sb + (O_W0Z  + j*HDIM)*4;
  const uint32_t aw0n  = sb + (O_W0N  + j*HDIM)*4;
  const uint32_t aw1xr = sb + (O_W1XR + j*HDIM)*4;
  const uint32_t aw1xz = sb + (O_W1XZ + j*HDIM)*4;
  const uint32_t aw1xn = sb + (O_W1XN + j*HDIM)*4;
  const uint32_t aw1hr = sb + (O_W1HR + j*HDIM)*4;
  const uint32_t aw1hz = sb + (O_W1HZ + j*HDIM)*4;
  const uint32_t aw1hn = sb + (O_W1HN + j*HDIM)*4;
  const uint32_t ah0b  = sb + (O_H0 + b*PITCH)*4;
  const uint32_t ah1b  = sb + (O_H1 + b*PITCH)*4;

  for (int t = 0; t < TSTEPS; t++) {
    const int p = t & 1, q = p ^ 1;

    // ================= phase A: layer-0 GRU cell =================
    if (tid < HS*NB) {
      unsigned long long ar = 0, az = 0, an = 0;
      const uint32_t ha = ah0b + p*HB*4;
      #pragma unroll 5
      for (int k = 0; k < HDIM; k += 4) {
        unsigned long long hA, hB, wA, wB;
        LDSV2(hA, hB, ha + k*4);
        LDSV2(wA, wB, aw0r + k*4); FMA2(ar, wA, hA); FMA2(ar, wB, hB);
        LDSV2(wA, wB, aw0z + k*4); FMA2(az, wA, hA); FMA2(az, wB, hB);
        LDSV2(wA, wB, aw0n + k*4); FMA2(an, wA, hA); FMA2(an, wB, hB);
      }
      float dr = red2(ar), dz = red2(az), dn = red2(an);
      // gx0 (8-wide input projection) + biases
      float xr = smem[O_BR0 + j], xz = smem[O_BZ0 + j], xn = smem[O_BN0X + j];
      #pragma unroll
      for (int c = 0; c < 8; c++) {
        float ic = smem[O_INB + b*8 + c];
        xr = fmaf(smem[O_WI0R + j*8 + c], ic, xr);
        xz = fmaf(smem[O_WI0Z + j*8 + c], ic, xz);
        xn = fmaf(smem[O_WI0N + j*8 + c], ic, xn);
      }
      float r = sigmoid_f(xr + dr);
      float z = sigmoid_f(xz + dz);
      float n = tanh_f(xn + r * (dn + smem[O_BN0H + j]));
      float h0old = smem[O_H0 + p*HB + b*PITCH + row0 + j];
      float h0n = n + z * (h0old - n);
      // broadcast new h0 slice to all 8 CTAs' next-parity buffer
      uint32_t la = sb + (O_H0 + q*HB + b*PITCH + row0 + j)*4;
      #pragma unroll
      for (int rr = 0; rr < CLSZ; rr++) {
        uint32_t ra;
        asm("mapa.shared::cluster.u32 %0, %1, %2;" : "=r"(ra) : "r"(la), "r"(rr));
        asm volatile("st.shared::cluster.f32 [%0], %1;" :: "r"(ra), "f"(h0n) : "memory");
      }
    }

    // prefetch next step's teacher-forcing input (x[b, t, 0:4])
    float4 xnext = make_float4(0.f, 0.f, 0.f, 0.f);
    if (tid < NB)
      xnext = *(const float4*)(x + ((size_t)(g*NB + tid) * TSTEPS + t) * 8);

    cluster_sync();   // h0_new complete everywhere

    if (tid < NB) {
      float* ib = smem + O_INB + tid*8;
      ib[0] = xnext.x; ib[1] = xnext.y; ib[2] = xnext.z; ib[3] = xnext.w;
    }

    // ================= phase B: layer-1 GRU cell =================
    if (tid < HS*NB) {
      unsigned long long axr = 0, axz = 0, axn = 0, ahr = 0, ahz = 0, ahn = 0;
      const uint32_t h0a = ah0b + q*HB*4;   // new h0
      const uint32_t h1a = ah1b + p*HB*4;   // current h1
      #pragma unroll 5
      for (int k = 0; k < HDIM; k += 4) {
        unsigned long long gA, gB, eA, eB, wA, wB;
        LDSV2(gA, gB, h0a + k*4);
        LDSV2(eA, eB, h1a + k*4);
        LDSV2(wA, wB, aw1xr + k*4); FMA2(axr, wA, gA); FMA2(axr, wB, gB);
        LDSV2(wA, wB, aw1xz + k*4); FMA2(axz, wA, gA); FMA2(axz, wB, gB);
        LDSV2(wA, wB, aw1xn + k*4); FMA2(axn, wA, gA); FMA2(axn, wB, gB);
        LDSV2(wA, wB, aw1hr + k*4); FMA2(ahr, wA, eA); FMA2(ahr, wB, eB);
        LDSV2(wA, wB, aw1hz + k*4); FMA2(ahz, wA, eA); FMA2(ahz, wB, eB);
        LDSV2(wA, wB, aw1hn + k*4); FMA2(ahn, wA, eA); FMA2(ahn, wB, eB);
      }
      float r = sigmoid_f(red2(axr) + red2(ahr) + smem[O_BR1 + j]);
      float z = sigmoid_f(red2(axz) + red2(ahz) + smem[O_BZ1 + j]);
      float n = tanh_f(red2(axn) + smem[O_BN1X + j] +
                       r * (red2(ahn) + smem[O_BN1H + j]));
      float h1old = smem[O_H1 + p*HB + b*PITCH + row0 + j];
      float h1n = n + z * (h1old - n);
      uint32_t la = sb + (O_H1 + q*HB + b*PITCH + row0 + j)*4;
      #pragma unroll
      for (int rr = 0; rr < CLSZ; rr++) {
        uint32_t ra;
        asm("mapa.shared::cluster.u32 %0, %1, %2;" : "=r"(ra) : "r"(la), "r"(rr));
        asm volatile("st.shared::cluster.f32 [%0], %1;" :: "r"(ra), "f"(h1n) : "memory");
      }
    }

    cluster_sync();   // h1_new complete everywhere

    // ================= output: this CTA handles batch index = rank =================
    if (tid < 128) {
      const int o = tid >> 5, lane = tid & 31;
      const float* h1row = smem + O_H1 + q*HB + (int)rank*PITCH;
      float acc = 0.f;
      #pragma unroll
      for (int k = lane; k < HDIM; k += 32)
        acc = fmaf(smem[O_WFC + o*HDIM + k], h1row[k], acc);
      #pragma unroll
      for (int off = 16; off; off >>= 1)
        acc += __shfl_xor_sync(0xffffffffu, acc, off);
      if (lane == 0) {
        float v = tanh_f(acc + smem[O_BFC + o]);
        out[((size_t)(g*NB + (int)rank) * TSTEPS + t) * 4 + o] = v;
      }
    }
  }
}

extern "C" void kernel_launch(void* const* d_in, const int* in_sizes, int n_in,
                              void* d_out, int out_size) {
  (void)in_sizes; (void)n_in; (void)out_size;
  const float* x     = (const float*)d_in[0];
  const float* W_ih0 = (const float*)d_in[1];
  const float* W_hh0 = (const float*)d_in[2];
  const float* b_ih0 = (const float*)d_in[3];
  const float* b_hh0 = (const float*)d_in[4];
  const float* W_ih1 = (const float*)d_in[5];
  const float* W_hh1 = (const float*)d_in[6];
  const float* b_ih1 = (const float*)d_in[7];
  const float* b_hh1 = (const float*)d_in[8];
  const float* W_fc  = (const float*)d_in[9];
  const float* b_fc  = (const float*)d_in[10];
  // d_in[11] = xlens (unused by reference)

  cudaFuncSetAttribute(gru2_kernel,
                       cudaFuncAttributeMaxDynamicSharedMemorySize, SMEM_BYTES);
  gru2_kernel<<<128, NTHR, SMEM_BYTES>>>(x, W_ih0, W_hh0, b_ih0, b_hh0,
                                         W_ih1, W_hh1, b_ih1, b_hh1,
                                         W_fc, b_fc, (float*)d_out);
}